// round 6
// baseline (speedup 1.0000x reference)
#include <cuda_runtime.h>
#include <cstddef>

// Problem constants (fixed by the dataset problem)
#define CC 32
#define HH 128
#define WW 512
#define PAD 40
#define DD (PAD + 1)
#define NROWS (CC * HH)      // 4096 (c,h) rows
#define GRID 1776            // 148 SMs x 12 resident CTAs = one full wave

// out[c,d,h,w] = in1[c,h,w] * (w >= d ? in2[c,h,w-d] : 0)
//
// Persistent grid: 1776 CTAs (one resident wave), each handling 2-3 (c,h)
// rows. Per row: in2 staged in double-buffered shared memory with a PAD-float
// zero apron (zeroed once); thread t owns the aligned float4 at w = 4t; the
// shifted in2 window slides one float left per disparity via the shuffle
// network (thread t's next b0 = thread t-1's current b3), lane 0 filling from
// shared. The next row's global loads are prefetched into registers BEFORE
// the current row's 41-store loop, so DRAM reads overlap the write stream and
// the per-row barrier never waits on load latency.
__global__ __launch_bounds__(128) void corr1d_pers_kernel(
    const float* __restrict__ in1,
    const float* __restrict__ in2,
    float* __restrict__ out)
{
    __shared__ float s2[2][PAD + WW];   // double buffer; [0,PAD) zero aprons

    const int t    = threadIdx.x;       // 0..127
    const int lane = t & 31;

    // Zero both aprons once (protected by the first per-row __syncthreads).
    if (t < PAD) {
        s2[0][t] = 0.0f;
        s2[1][t] = 0.0f;
    }

    const size_t plane_stride_v4 = (size_t)HH * WW / 4;   // 16384 float4s
    const int base = PAD + 4 * t;       // s2 index of b0 at d=0

    int row = blockIdx.x;

    // Prefetch first row.
    float4 a_nxt, v_nxt;
    if (row < NROWS) {
        a_nxt = reinterpret_cast<const float4*>(in1 + (size_t)row * WW)[t];
        v_nxt = reinterpret_cast<const float4*>(in2 + (size_t)row * WW)[t];
    }

    int buf = 0;
    for (; row < NROWS; row += GRID) {
        const float4 a = a_nxt;
        const float4 v = v_nxt;

        // Prefetch next row while this row's store loop runs.
        const int nrow = row + GRID;
        if (nrow < NROWS) {
            a_nxt = reinterpret_cast<const float4*>(in1 + (size_t)nrow * WW)[t];
            v_nxt = reinterpret_cast<const float4*>(in2 + (size_t)nrow * WW)[t];
        }

        // Stage in2 row into this row's buffer (16B-aligned: PAD*4 = 160 B).
        reinterpret_cast<float4*>(s2[buf] + PAD)[t] = v;
        __syncthreads();   // also protects buffer reuse (2 rows apart)

        const float* sb = s2[buf];

        // d=0 window from the staged row.
        float b0 = sb[base + 0];
        float b1 = sb[base + 1];
        float b2 = sb[base + 2];
        float b3 = sb[base + 3];

        const int c = row / HH;
        const int h = row % HH;
        float4* po = reinterpret_cast<float4*>(
            out + ((size_t)(c * DD) * HH + h) * WW) + t;

        #pragma unroll
        for (int d = 0; d <= PAD; ++d) {
            float4 r;
            r.x = a.x * b0;
            r.y = a.y * b1;
            r.z = a.z * b2;
            r.w = a.w * b3;
            __stcs(po + (size_t)d * plane_stride_v4, r);   // streaming store

            if (d < PAD) {
                // Next b0 = sb[base - d - 1] = previous lane's current b3.
                float carry = __shfl_up_sync(0xffffffffu, b3, 1);
                if (lane == 0) carry = sb[base - d - 1];   // warp boundary
                b3 = b2;
                b2 = b1;
                b1 = b0;
                b0 = carry;
            }
        }

        buf ^= 1;
    }
}

extern "C" void kernel_launch(void* const* d_in, const int* in_sizes, int n_in,
                              void* d_out, int out_size)
{
    const float* in1 = (const float*)d_in[0];
    const float* in2 = (const float*)d_in[1];
    float* out = (float*)d_out;

    corr1d_pers_kernel<<<GRID, WW / 4>>>(in1, in2, out);
}

// round 7
// speedup vs baseline: 1.0280x; 1.0280x over previous
#include <cuda_runtime.h>
#include <cstddef>

// Problem constants (fixed by the dataset problem)
#define CC 32
#define HH 128
#define WW 512
#define PAD 40
#define DD (PAD + 1)

// out[c,d,h,w] = in1[c,h,w] * (w >= d ? in2[c,h,w-d] : 0)
//
// One CTA per (c,h) row (4096 CTAs, 128 threads). in2 row staged once into
// shared memory with a PAD-float zero apron. Thread t owns the aligned float4
// at w = 4t. The shifted in2 window slides one float left per disparity via
// the shuffle network (thread t's next b0 = thread t-1's current b3); only
// lane 0 reads shared in the loop, so in-loop L1tex traffic is stores-only.
//
// __launch_bounds__(128, 16): the rotating-window loop has small live state
// (fits in 32 regs without spilling), so cap regs to get 16 CTAs / 64 warps
// per SM — more independent streaming-store streams to feed the HBM write
// path, which is the binding resource.
__global__ __launch_bounds__(128, 16) void corr1d_row_kernel(
    const float* __restrict__ in1,
    const float* __restrict__ in2,
    float* __restrict__ out)
{
    __shared__ float s2[PAD + WW];   // 552 floats; [0,PAD) is the zero apron

    const int row  = blockIdx.x;     // (c,h) in [0, C*H)
    const int t    = threadIdx.x;    // 0..127
    const int lane = t & 31;
    const int c    = row / HH;
    const int h    = row % HH;

    // Stage rows. PAD*4 = 160 bytes, 16B-aligned, so float4 stores into
    // s2+PAD are legal.
    const float4 a = reinterpret_cast<const float4*>(in1 + (size_t)row * WW)[t];
    if (t < PAD) s2[t] = 0.0f;
    reinterpret_cast<float4*>(s2 + PAD)[t] =
        reinterpret_cast<const float4*>(in2 + (size_t)row * WW)[t];
    __syncthreads();

    // Output base for d=0 plane of this (c,h) row; planes are HH*WW apart.
    float4* po = reinterpret_cast<float4*>(
        out + ((size_t)(c * DD) * HH + h) * WW) + t;
    const size_t plane_stride_v4 = (size_t)HH * WW / 4;   // 16384 float4s

    // d=0 window: one aligned LDS.128.
    float4 b = reinterpret_cast<const float4*>(s2 + PAD)[t];
    float b0 = b.x, b1 = b.y, b2 = b.z, b3 = b.w;

    const int base = PAD + 4 * t;    // s2 index of b0 at d=0

    #pragma unroll
    for (int d = 0; d <= PAD; ++d) {
        float4 r;
        r.x = a.x * b0;
        r.y = a.y * b1;
        r.z = a.z * b2;
        r.w = a.w * b3;
        __stcs(po + (size_t)d * plane_stride_v4, r);   // streaming store

        if (d < PAD) {
            // Next b0 = s2[base - d - 1] = previous lane's current b3.
            float carry = __shfl_up_sync(0xffffffffu, b3, 1);
            if (lane == 0) carry = s2[base - d - 1];   // warp-boundary fill
            b3 = b2;
            b2 = b1;
            b1 = b0;
            b0 = carry;
        }
    }
}

extern "C" void kernel_launch(void* const* d_in, const int* in_sizes, int n_in,
                              void* d_out, int out_size)
{
    const float* in1 = (const float*)d_in[0];
    const float* in2 = (const float*)d_in[1];
    float* out = (float*)d_out;

    corr1d_row_kernel<<<CC * HH, WW / 4>>>(in1, in2, out);
}